// round 3
// baseline (speedup 1.0000x reference)
#include <cuda_runtime.h>
#include <cuda_bf16.h>
#include <cstdint>

#define NROWS 8192
#define FDIM  256
#define KCH   64
#define MT    64
#define NCHUNK (NROWS / KCH)   // 128

// __device__ scratch (allocation-free rule)
__device__ __align__(16) __nv_bfloat16 g_xtT[FDIM * NROWS]; // [f][i] bf16 = B^T (n-major rows, k contiguous)
__device__ __align__(16) float g_p[NROWS];
__device__ __align__(16) float g_q[NROWS];

static __device__ __forceinline__ uint32_t smem_u32(const void* p) {
    uint32_t a;
    asm("{ .reg .u64 t; cvta.to.shared.u64 t, %1; cvt.u32.u64 %0, t; }" : "=r"(a) : "l"(p));
    return a;
}
static __device__ __forceinline__ uint32_t sw128(uint32_t o) { return o ^ ((o >> 3) & 0x70); }
static __device__ __forceinline__ float frcp(float u) {
    float r; asm("rcp.approx.f32 %0, %1;" : "=f"(r) : "f"(u)); return r;
}
static __device__ __forceinline__ void ldsm4(uint32_t* r, uint32_t addr) {
    asm volatile("ldmatrix.sync.aligned.m8n8.x4.shared.b16 {%0,%1,%2,%3}, [%4];"
        : "=r"(r[0]), "=r"(r[1]), "=r"(r[2]), "=r"(r[3]) : "r"(addr));
}
static __device__ __forceinline__ void mma16816(float* c, const uint32_t* a,
                                                uint32_t b0, uint32_t b1) {
    asm volatile("mma.sync.aligned.m16n8k16.row.col.f32.bf16.bf16.f32 "
        "{%0,%1,%2,%3}, {%4,%5,%6,%7}, {%8,%9}, {%0,%1,%2,%3};"
        : "+f"(c[0]), "+f"(c[1]), "+f"(c[2]), "+f"(c[3])
        : "r"(a[0]), "r"(a[1]), "r"(a[2]), "r"(a[3]), "r"(b0), "r"(b1));
}
static __device__ __forceinline__ void cpasync16(uint32_t dst, const void* src) {
    asm volatile("cp.async.cg.shared.global [%0], [%1], 16;" :: "r"(dst), "l"(src) : "memory");
}

// ---------------------------------------------------------------------------
// Kernel 1: logmap0 -> xtT bf16 (staged through smem for 16B stores), p, q.
// One warp per row; 8 rows per block.
// ---------------------------------------------------------------------------
__global__ __launch_bounds__(256) void k1_logmap(
    const float* __restrict__ x, const float* __restrict__ wv,
    const float* __restrict__ b_att)
{
    __shared__ __nv_bfloat16 sxt[FDIM * 8];   // [f][8 rows]
    const int w = threadIdx.x >> 5, l = threadIdx.x & 31;
    const int row = blockIdx.x * 8 + w;
    const float* xr = x + (size_t)row * FDIM;

    float xv[8];
#pragma unroll
    for (int t = 0; t < 8; t++) xv[t] = __ldg(xr + l + 32 * t);

    float ss = 0.f;
#pragma unroll
    for (int t = 0; t < 8; t++) {
        float v = (t == 0 && l == 0) ? 0.f : xv[t];
        ss += v * v;
    }
#pragma unroll
    for (int o = 16; o; o >>= 1) ss += __shfl_xor_sync(~0u, ss, o);

    const float x0 = __shfl_sync(~0u, xv[0], 0);
    const float yn = fmaxf(sqrtf(ss), 1e-15f);
    const float th = fmaxf(x0, 1.0f + 1e-7f);
    const float s = acoshf(th) / yn;

    float sl = 0.f, sr = 0.f;
#pragma unroll
    for (int t = 0; t < 8; t++) {
        const int f = l + 32 * t;
        const float xt = (f == 0) ? 0.f : s * xv[t];
        xv[t] = xt;
        sl += xt * __ldg(wv + f);
        sr += xt * __ldg(wv + FDIM + f);
    }
#pragma unroll
    for (int o = 16; o; o >>= 1) {
        sl += __shfl_xor_sync(~0u, sl, o);
        sr += __shfl_xor_sync(~0u, sr, o);
    }
    if (l == 0) {
        g_p[row] = __expf(-(sl + b_att[0]));
        g_q[row] = __expf(-sr);
    }
#pragma unroll
    for (int t = 0; t < 8; t++) {
        const int f = l + 32 * t;
        sxt[f * 8 + w] = __float2bfloat16(xv[t]);
    }
    __syncthreads();
    // thread tid writes feature tid's 8-row slab as one 16B store
    const int f = threadIdx.x;
    *reinterpret_cast<uint4*>(&g_xtT[(size_t)f * NROWS + blockIdx.x * 8]) =
        *reinterpret_cast<const uint4*>(&sxt[f * 8]);
}

// ---------------------------------------------------------------------------
// Kernel 2: fused att generation + mma.sync bf16 GEMM + expmap0/proj epilogue
// grid = 128 CTAs (M tiles of 64), 256 threads = 8 warps (2 mw x 4 nw).
// SMEM: A[2] 8KB @0, B^T[2] 32KB @16384, reduction scratch @81920.
// ---------------------------------------------------------------------------
#define SM_A    0u
#define SM_B    16384u
#define SM_PART 81920
#define SM_CHS  82944
#define SM_SCS  83200
#define SMEM_BYTES 83456

__global__ __launch_bounds__(256, 1) void k2_agg(
    const float* __restrict__ adj, float* __restrict__ out)
{
    extern __shared__ char smem[];
    const uint32_t sb = smem_u32(smem);
    const int tid = threadIdx.x;
    const int w = tid >> 5, l = tid & 31;
    const int mw = w >> 2, nw = w & 3;
    const int g = l >> 2, tig = l & 3;
    const int m0 = blockIdx.x * MT;

    float c[2][8][4];
#pragma unroll
    for (int mf = 0; mf < 2; mf++)
#pragma unroll
        for (int nf = 0; nf < 8; nf++)
#pragma unroll
            for (int i = 0; i < 4; i++) c[mf][nf][i] = 0.f;

    // ldmatrix lane geometry
    const int a_row = mw * 32 + ((l >> 3) & 1) * 8 + (l & 7);  // + mf*16
    const int a_kh  = (l >> 4) * 8;
    const int b_row = nw * 64 + ((l >> 4) & 1) * 8 + (l & 7);  // + nf2*16
    const int b_kh  = ((l >> 3) & 1) * 8;

    // A producer geometry: thread -> (m row, 16-wide k quarter)
    const int am  = tid >> 2;
    const int akq = tid & 3;
    const float* adjrow = adj + (size_t)(m0 + am) * NROWS + akq * 16;
    const float pm = __ldg(&g_p[m0 + am]);

    // ---- prologue: B chunk 0 (cp.async) + adj chunk 0 (registers)
#pragma unroll
    for (int j = 0; j < 8; j++) {
        const int id = tid + 256 * j;
        const int n = id >> 3, kb = id & 7;
        cpasync16(sb + SM_B + sw128((uint32_t)(n * 128 + kb * 16)),
                  &g_xtT[(size_t)n * NROWS + kb * 8]);
    }
    asm volatile("cp.async.commit_group;" ::: "memory");
    float4 ar[4];
#pragma unroll
    for (int i = 0; i < 4; i++)
        ar[i] = __ldg(reinterpret_cast<const float4*>(adjrow) + i);

    for (int cch = 0; cch < NCHUNK; cch++) {
        const uint32_t buf = (uint32_t)(cch & 1);
        const int k0 = cch * KCH;

        // 1. A tile: att = adj * rcp(1 + p*q) -> bf16, SW128 rows of 128B
        {
            const uint32_t Ab = sb + SM_A + buf * 8192u;
#pragma unroll
            for (int i = 0; i < 4; i++) {
                const float4 qv = __ldg(reinterpret_cast<const float4*>(
                    &g_q[k0 + akq * 16]) + i);
                const float a0 = ar[i].x * frcp(fmaf(pm, qv.x, 1.0f));
                const float a1 = ar[i].y * frcp(fmaf(pm, qv.y, 1.0f));
                const float a2 = ar[i].z * frcp(fmaf(pm, qv.z, 1.0f));
                const float a3 = ar[i].w * frcp(fmaf(pm, qv.w, 1.0f));
                __nv_bfloat162 p01 = __floats2bfloat162_rn(a0, a1);
                __nv_bfloat162 p23 = __floats2bfloat162_rn(a2, a3);
                const uint32_t off = Ab + sw128((uint32_t)(am * 128 + akq * 32 + i * 8));
                asm volatile("st.shared.v2.b32 [%0], {%1, %2};"
                    :: "r"(off),
                       "r"(*reinterpret_cast<uint32_t*>(&p01)),
                       "r"(*reinterpret_cast<uint32_t*>(&p23)) : "memory");
            }
        }

        // 2. own cp.async for B(cch) complete, 3. all threads' STS + copies visible
        asm volatile("cp.async.wait_group 0;" ::: "memory");
        __syncthreads();

        // 4+5. prefetch next chunk (B via cp.async to other buffer, adj to regs)
        if (cch + 1 < NCHUNK) {
            const int k1 = k0 + KCH;
            const uint32_t Bn = sb + SM_B + (buf ^ 1u) * 32768u;
#pragma unroll
            for (int j = 0; j < 8; j++) {
                const int id = tid + 256 * j;
                const int n = id >> 3, kb = id & 7;
                cpasync16(Bn + sw128((uint32_t)(n * 128 + kb * 16)),
                          &g_xtT[(size_t)n * NROWS + k1 + kb * 8]);
            }
            asm volatile("cp.async.commit_group;" ::: "memory");
#pragma unroll
            for (int i = 0; i < 4; i++)
                ar[i] = __ldg(reinterpret_cast<const float4*>(adjrow + k1) + i);
        }

        // 6. MMA over this chunk (K=64 -> 4 k16 steps)
        {
            const uint32_t Ab = sb + SM_A + buf * 8192u;
            const uint32_t Bb = sb + SM_B + buf * 32768u;
#pragma unroll
            for (int ks = 0; ks < 4; ks++) {
                uint32_t afr[2][4];
#pragma unroll
                for (int mf = 0; mf < 2; mf++)
                    ldsm4(afr[mf], Ab + sw128((uint32_t)((a_row + mf * 16) * 128
                                                         + (ks * 16 + a_kh) * 2)));
                uint32_t bfr[4][4];
#pragma unroll
                for (int nf2 = 0; nf2 < 4; nf2++)
                    ldsm4(bfr[nf2], Bb + sw128((uint32_t)((b_row + nf2 * 16) * 128
                                                          + (ks * 16 + b_kh) * 2)));
#pragma unroll
                for (int mf = 0; mf < 2; mf++)
#pragma unroll
                    for (int nf = 0; nf < 8; nf++)
                        mma16816(c[mf][nf], afr[mf],
                                 bfr[nf >> 1][(nf & 1) * 2],
                                 bfr[nf >> 1][(nf & 1) * 2 + 1]);
            }
        }
    }

    // ---- Epilogue: row norms across n-warps, then cosh/sinh scale + store.
    float* part = reinterpret_cast<float*>(smem + SM_PART);  // [64][4]
    float* chs  = reinterpret_cast<float*>(smem + SM_CHS);
    float* scs  = reinterpret_cast<float*>(smem + SM_SCS);

    float ssr[4];   // rows: mf*2 + (hi?)
#pragma unroll
    for (int mf = 0; mf < 2; mf++) {
        float slo = 0.f, shi = 0.f;
#pragma unroll
        for (int nf = 0; nf < 8; nf++) {
            slo += c[mf][nf][0] * c[mf][nf][0] + c[mf][nf][1] * c[mf][nf][1];
            shi += c[mf][nf][2] * c[mf][nf][2] + c[mf][nf][3] * c[mf][nf][3];
        }
        ssr[mf * 2] = slo; ssr[mf * 2 + 1] = shi;
    }
#pragma unroll
    for (int i = 0; i < 4; i++) {
        ssr[i] += __shfl_xor_sync(~0u, ssr[i], 1);
        ssr[i] += __shfl_xor_sync(~0u, ssr[i], 2);
    }
    if (tig == 0) {
#pragma unroll
        for (int mf = 0; mf < 2; mf++)
#pragma unroll
            for (int h = 0; h < 2; h++)
                part[(mw * 32 + mf * 16 + g + h * 8) * 4 + nw] = ssr[mf * 2 + h];
    }
    __syncthreads();
    if (tid < 64) {
        const float ss = part[tid * 4] + part[tid * 4 + 1]
                       + part[tid * 4 + 2] + part[tid * 4 + 3];
        const float nrm = fmaxf(sqrtf(ss), 1e-15f);
        const float e = expf(nrm), ei = 1.0f / e;
        chs[tid] = 0.5f * (e + ei);
        scs[tid] = (nrm < 1e-6f) ? 1.0f : 0.5f * (e - ei) / nrm;
    }
    __syncthreads();

#pragma unroll
    for (int mf = 0; mf < 2; mf++)
#pragma unroll
        for (int h = 0; h < 2; h++) {
            const int row = mw * 32 + mf * 16 + g + h * 8;
            const float sc = scs[row];
            float* orow = out + (size_t)(m0 + row) * FDIM;
#pragma unroll
            for (int nf = 0; nf < 8; nf++) {
                const int col = nw * 64 + nf * 8 + 2 * tig;
                float v0 = c[mf][nf][h * 2] * sc;
                const float v1 = c[mf][nf][h * 2 + 1] * sc;
                if (col == 0) v0 = chs[row];
                float2 v = make_float2(v0, v1);
                *reinterpret_cast<float2*>(orow + col) = v;
            }
        }
}

extern "C" void kernel_launch(void* const* d_in, const int* in_sizes, int n_in,
                              void* d_out, int out_size) {
    const float* x     = (const float*)d_in[0];
    const float* adj   = (const float*)d_in[1];
    const float* w_att = (const float*)d_in[2];
    const float* b_att = (const float*)d_in[3];
    float* out = (float*)d_out;

    static int attr_done = 0;
    if (!attr_done) {
        cudaFuncSetAttribute(k2_agg, cudaFuncAttributeMaxDynamicSharedMemorySize,
                             SMEM_BYTES);
        attr_done = 1;
    }
    k1_logmap<<<NROWS / 8, 256>>>(x, w_att, b_att);
    k2_agg<<<NROWS / MT, 256, SMEM_BYTES>>>(adj, out);
}